// round 14
// baseline (speedup 1.0000x reference)
#include <cuda_runtime.h>
#include <cuda_bf16.h>
#include <cuda_fp16.h>
#include <math.h>
#include <stdint.h>

#define N_NODES 50000
#define N_EDGES 800000
#define HID     128
#define OUT_CH  64
#define N_LAYERS 4
#define CATW    (HID * N_LAYERS)   // 512
#define CATU    (CATW / 2)         // 256 u32 per row

#define TILES      391            // ceil(50000/128)
#define HALF_TILES 196
#define HALF_NODES (HALF_TILES * 128)   // 25088

// weight regions in split-u32 space
#define WU_IN   0
#define WU_C    8192
#define WU_OUT  (WU_C + 4 * 8192)
#define WU_TOT  (WU_OUT + 16384)   // 57344

// ================= device scratch =================
__device__ __align__(16) uint32_t g_x0h[(size_t)N_NODES * HID / 2];
__device__ __align__(16) uint32_t g_x0l[(size_t)N_NODES * HID / 2];
__device__ __align__(16) uint32_t g_hf[(size_t)N_NODES * HID / 2];   // h as half2
__device__ __align__(16) uint32_t g_cath[(size_t)N_NODES * CATU];
__device__ __align__(16) uint32_t g_catl[(size_t)N_NODES * CATU];
__device__ __align__(16) uint32_t g_wh[WU_TOT];
__device__ __align__(16) uint32_t g_wl[WU_TOT];
__device__ int    g_degi[N_NODES];
__device__ int    g_off[N_NODES + 1];
__device__ int    g_cur[N_NODES];
__device__ float2 g_adj[N_EDGES];
__device__ int    g_is64;

#define SCAN_B 256
#define NBLK ((N_NODES + SCAN_B - 1) / SCAN_B)   // 196
__device__ int g_bsum[NBLK];

// ================= helpers =================
__device__ __forceinline__ uint32_t pack2(float lo_elem, float hi_elem) {
    __nv_bfloat162 t = __floats2bfloat162_rn(lo_elem, hi_elem);
    return *(uint32_t*)&t;
}
__device__ __forceinline__ void hilo(float x, float& h, float& l) {
    float hf = __bfloat162float(__float2bfloat16_rn(x));
    h = hf;
    l = x - hf;
}
__device__ __forceinline__ void mma16816(float* c, const uint32_t* a, const uint32_t* b) {
    asm volatile(
        "mma.sync.aligned.m16n8k16.row.col.f32.bf16.bf16.f32 "
        "{%0,%1,%2,%3}, {%4,%5,%6,%7}, {%8,%9}, {%0,%1,%2,%3};"
        : "+f"(c[0]), "+f"(c[1]), "+f"(c[2]), "+f"(c[3])
        : "r"(a[0]), "r"(a[1]), "r"(a[2]), "r"(a[3]), "r"(b[0]), "r"(b[1]));
}
__device__ __forceinline__ uint32_t smem_u32(const void* p) {
    uint32_t a;
    asm("{ .reg .u64 t; cvta.to.shared.u64 t, %1; cvt.u32.u64 %0, t; }" : "=r"(a) : "l"(p));
    return a;
}
__device__ __forceinline__ void cp_async16(uint32_t saddr, const void* gptr, bool pred) {
    int sz = pred ? 16 : 0;
    asm volatile("cp.async.cg.shared.global [%0], [%1], 16, %2;"
                 :: "r"(saddr), "l"(gptr), "r"(sz));
}
#define CP_COMMIT() asm volatile("cp.async.commit_group;" ::: "memory")
#define CP_WAIT(n)  asm volatile("cp.async.wait_group %0;" :: "n"(n) : "memory")

// ================= fused init: degree=1 + weight split + dtype detect =================
__global__ void fused_init_kernel(const void* ei,
                                  const float* __restrict__ W_in,
                                  const float* __restrict__ Wc,
                                  const float* __restrict__ W_out) {
    int t = blockIdx.x * blockDim.x + threadIdx.x;
    if (t < N_NODES) g_degi[t] = 1;
    if (t < WU_TOT) {
        const float* src;
        int rt;
        if (t < WU_C) { src = W_in; rt = t; }
        else if (t < WU_OUT) { src = Wc; rt = t - WU_C; }
        else { src = W_out; rt = t - WU_OUT; }
        float a = src[2 * rt], b = src[2 * rt + 1];
        float ha, la, hb, lb;
        hilo(a, ha, la);
        hilo(b, hb, lb);
        g_wh[t] = pack2(ha, hb);
        g_wl[t] = pack2(la, lb);
    }
    if (blockIdx.x == 0) {
        const long long* p = (const long long*)ei;
        int bad = 0;
        for (int i = threadIdx.x; i < 1024; i += blockDim.x) {
            long long v = p[i];
            if (v < 0 || v >= (long long)N_NODES) bad = 1;
        }
        bad = __syncthreads_or(bad);
        if (threadIdx.x == 0) g_is64 = bad ? 0 : 1;
    }
}

__global__ void degcount_kernel(const void* ei) {
    int e = blockIdx.x * blockDim.x + threadIdx.x;
    if (e >= N_EDGES) return;
    int d;
    if (g_is64) d = (int)((const long long*)ei)[N_EDGES + e];
    else        d = ((const int*)ei)[N_EDGES + e];
    atomicAdd(&g_degi[d], 1);
}

// ================= proven 3-phase scan =================
__global__ void scan1_kernel() {
    __shared__ int s[SCAN_B];
    int t = threadIdx.x;
    int v = blockIdx.x * SCAN_B + t;
    s[t] = (v < N_NODES) ? (g_degi[v] - 1) : 0;
    __syncthreads();
    for (int off = SCAN_B / 2; off > 0; off >>= 1) {
        if (t < off) s[t] += s[t + off];
        __syncthreads();
    }
    if (t == 0) g_bsum[blockIdx.x] = s[0];
}
__global__ void scan2_kernel() {
    __shared__ int s[SCAN_B];
    int t = threadIdx.x;
    int v = (t < NBLK) ? g_bsum[t] : 0;
    s[t] = v;
    __syncthreads();
    for (int off = 1; off < SCAN_B; off <<= 1) {
        int a = (t >= off) ? s[t - off] : 0;
        __syncthreads();
        s[t] += a;
        __syncthreads();
    }
    if (t < NBLK) g_bsum[t] = s[t] - v;
    if (t == NBLK - 1) g_off[N_NODES] = s[t];
}
__global__ void scan3_kernel() {
    __shared__ int s[SCAN_B];
    int t = threadIdx.x;
    int v = blockIdx.x * SCAN_B + t;
    int d = (v < N_NODES) ? (g_degi[v] - 1) : 0;
    s[t] = d;
    __syncthreads();
    for (int off = 1; off < SCAN_B; off <<= 1) {
        int a = (t >= off) ? s[t - off] : 0;
        __syncthreads();
        s[t] += a;
        __syncthreads();
    }
    if (v < N_NODES) {
        g_off[v] = g_bsum[blockIdx.x] + s[t] - d;
        g_cur[v] = 0;
    }
}
__global__ void fill_kernel(const void* ei) {
    int e = blockIdx.x * blockDim.x + threadIdx.x;
    if (e >= N_EDGES) return;
    int s, d;
    if (g_is64) {
        const long long* p = (const long long*)ei;
        s = (int)p[e];
        d = (int)p[N_EDGES + e];
    } else {
        const int* p = (const int*)ei;
        s = p[e];
        d = p[N_EDGES + e];
    }
    int pos = g_off[d] + atomicAdd(&g_cur[d], 1);
    float nm = rsqrtf((float)g_degi[s] * (float)g_degi[d]);
    g_adj[pos] = make_float2(__int_as_float(s), nm);
}

// ================= pipelined bf16x2-split GEMM (BM=128, cp.async double buffer) =================
// EPI: 0 -> fp32 store (bias), 1 -> fp16 half2 store.  tile_base: row-tile offset.
#define PADU 20

template <int NN, int EPI>
__global__ void __launch_bounds__(256) mma_gemm_pipe(
    const uint32_t* __restrict__ Ah, const uint32_t* __restrict__ Al, int lda_u,
    const uint32_t* __restrict__ Bh, const uint32_t* __restrict__ Bl, int ldb_u,
    const float* __restrict__ bias,
    float* __restrict__ Cf, int ldc,
    uint32_t* __restrict__ Ch, int ldh_u,
    int M, int K, int tile_base)
{
    extern __shared__ uint32_t dyn[];
    constexpr int OA_LO = 128 * PADU;
    constexpr int OB_HI = 2 * 128 * PADU;
    constexpr int OB_LO = OB_HI + NN * PADU;
    constexpr int BUF_U = OB_LO + NN * PADU;

    const int tid = threadIdx.x;
    const int wid = tid >> 5;
    const int lane = tid & 31;
    const int gr = lane >> 2;
    const int gc = lane & 3;
    const int warp_m = wid >> 1;
    const int warp_n = wid & 1;
    const int m0 = (blockIdx.x + tile_base) * 128;
    constexpr int NT = NN / 16;

    const uint32_t sbase = smem_u32(dyn);
    const int chunks = K >> 5;

    float acc[2][NT][4];
#pragma unroll
    for (int mt = 0; mt < 2; mt++)
#pragma unroll
        for (int nt = 0; nt < NT; nt++)
#pragma unroll
            for (int j = 0; j < 4; j++) acc[mt][nt][j] = 0.0f;

    auto stage = [&](int c, int buf) {
        const int k0u = c << 4;
        const uint32_t sb = sbase + (uint32_t)buf * BUF_U * 4;
#pragma unroll
        for (int it = 0; it < 2; it++) {
            int idx = tid + it * 256;
            int row = idx >> 2, j = idx & 3;
            bool ok = (m0 + row < M);
            size_t go = ok ? ((size_t)(m0 + row) * lda_u + k0u + j * 4) : 0;
            uint32_t so = (uint32_t)(row * PADU + j * 4) * 4;
            cp_async16(sb + so, Ah + go, ok);
            cp_async16(sb + OA_LO * 4 + so, Al + go, ok);
        }
#pragma unroll
        for (int it = 0; it < NN / 64; it++) {
            int idx = tid + it * 256;
            int row = idx >> 2, j = idx & 3;
            size_t go = (size_t)row * ldb_u + k0u + j * 4;
            uint32_t so = (uint32_t)(row * PADU + j * 4) * 4;
            cp_async16(sb + OB_HI * 4 + so, Bh + go, true);
            cp_async16(sb + OB_LO * 4 + so, Bl + go, true);
        }
        CP_COMMIT();
    };

    stage(0, 0);

    for (int c = 0; c < chunks; c++) {
        const int cur = c & 1;
        if (c + 1 < chunks) {
            stage(c + 1, cur ^ 1);
            CP_WAIT(1);
        } else {
            CP_WAIT(0);
        }
        __syncthreads();

        const uint32_t* sAh = dyn + cur * BUF_U;
        const uint32_t* sAl = sAh + OA_LO;
        const uint32_t* sBh = dyn + cur * BUF_U + OB_HI;
        const uint32_t* sBl = dyn + cur * BUF_U + OB_LO;

#pragma unroll
        for (int s = 0; s < 2; s++) {
            const int kc = s * 8 + gc;
            uint32_t ah[2][4], al[2][4];
#pragma unroll
            for (int mt = 0; mt < 2; mt++) {
                int r = warp_m * 32 + mt * 16 + gr;
                ah[mt][0] = sAh[r * PADU + kc];
                ah[mt][1] = sAh[(r + 8) * PADU + kc];
                ah[mt][2] = sAh[r * PADU + kc + 4];
                ah[mt][3] = sAh[(r + 8) * PADU + kc + 4];
                al[mt][0] = sAl[r * PADU + kc];
                al[mt][1] = sAl[(r + 8) * PADU + kc];
                al[mt][2] = sAl[r * PADU + kc + 4];
                al[mt][3] = sAl[(r + 8) * PADU + kc + 4];
            }
#pragma unroll
            for (int nt = 0; nt < NT; nt++) {
                int n = warp_n * (NN / 2) + nt * 8 + gr;
                uint32_t bh[2], bl[2];
                bh[0] = sBh[n * PADU + kc];
                bh[1] = sBh[n * PADU + kc + 4];
                bl[0] = sBl[n * PADU + kc];
                bl[1] = sBl[n * PADU + kc + 4];
#pragma unroll
                for (int mt = 0; mt < 2; mt++) {
                    mma16816(acc[mt][nt], ah[mt], bh);
                    mma16816(acc[mt][nt], ah[mt], bl);
                    mma16816(acc[mt][nt], al[mt], bh);
                }
            }
        }
        __syncthreads();
    }

#pragma unroll
    for (int mt = 0; mt < 2; mt++) {
#pragma unroll
        for (int nt = 0; nt < NT; nt++) {
            int col = warp_n * (NN / 2) + nt * 8 + 2 * gc;
            float b0 = __ldg(bias + col);
            float b1 = __ldg(bias + col + 1);
#pragma unroll
            for (int half = 0; half < 2; half++) {
                int r = m0 + warp_m * 32 + mt * 16 + gr + half * 8;
                if (r >= M) continue;
                float ox = acc[mt][nt][2 * half + 0] + b0;
                float oy = acc[mt][nt][2 * half + 1] + b1;
                if (EPI == 1) {
                    __half2 p = __floats2half2_rn(ox, oy);
                    Ch[(size_t)r * ldh_u + col / 2] = *(uint32_t*)&p;
                } else {
                    *(float2*)(Cf + (size_t)r * ldc + col) = make_float2(ox, oy);
                }
            }
        }
    }
}

// ================= input-projection GEMM: pipelined (reg-prefetch A, cp.async B) =================
__global__ void __launch_bounds__(256) mma_gemm_inproj(
    const float* __restrict__ A,
    const uint32_t* __restrict__ Bh, const uint32_t* __restrict__ Bl,
    const float* __restrict__ bias,
    uint32_t* __restrict__ Chi, uint32_t* __restrict__ Clo,
    int M)
{
    constexpr int NN = 128;
    constexpr int K = 128;
    extern __shared__ uint32_t dyn[];
    constexpr int OA_LO = 128 * PADU;
    constexpr int OB_HI = 2 * 128 * PADU;
    constexpr int OB_LO = OB_HI + NN * PADU;
    constexpr int BUF_U = OB_LO + NN * PADU;

    const int tid = threadIdx.x;
    const int wid = tid >> 5;
    const int lane = tid & 31;
    const int gr = lane >> 2;
    const int gc = lane & 3;
    const int warp_m = wid >> 1;
    const int warp_n = wid & 1;
    const int m0 = blockIdx.x * 128;
    constexpr int NT = NN / 16;

    const uint32_t sbase = smem_u32(dyn);

    float acc[2][NT][4];
#pragma unroll
    for (int mt = 0; mt < 2; mt++)
#pragma unroll
        for (int nt = 0; nt < NT; nt++)
#pragma unroll
            for (int j = 0; j < 4; j++) acc[mt][nt][j] = 0.0f;

    const int arow = tid >> 1;
    const int aq = (tid & 1) * 4;
    float4 pa[4];
    auto loadA = [&](int c) {
        bool ok = (m0 + arow < M);
        const float* base = A + (size_t)(m0 + arow) * K + c * 32 + aq * 4;
#pragma unroll
        for (int j = 0; j < 4; j++)
            pa[j] = ok ? *(const float4*)(base + j * 4) : make_float4(0, 0, 0, 0);
    };
    auto stageA = [&](int buf) {
        uint32_t* sA = dyn + buf * BUF_U;
        uint32_t* sAlo = sA + OA_LO;
#pragma unroll
        for (int j = 0; j < 4; j++) {
            float h0, h1, h2, h3, l0, l1, l2, l3;
            hilo(pa[j].x, h0, l0); hilo(pa[j].y, h1, l1);
            hilo(pa[j].z, h2, l2); hilo(pa[j].w, h3, l3);
            int base = arow * PADU + 2 * (aq + j);
            sA[base + 0] = pack2(h0, h1);
            sA[base + 1] = pack2(h2, h3);
            sAlo[base + 0] = pack2(l0, l1);
            sAlo[base + 1] = pack2(l2, l3);
        }
    };
    auto stageB = [&](int c, int buf) {
        const int k0u = c << 4;
        const uint32_t sb = sbase + (uint32_t)buf * BUF_U * 4;
#pragma unroll
        for (int it = 0; it < 2; it++) {
            int idx = tid + it * 256;
            int row = idx >> 2, j = idx & 3;
            size_t go = (size_t)row * 64 + k0u + j * 4;
            uint32_t so = (uint32_t)(row * PADU + j * 4) * 4;
            cp_async16(sb + OB_HI * 4 + so, Bh + go, true);
            cp_async16(sb + OB_LO * 4 + so, Bl + go, true);
        }
        CP_COMMIT();
    };

    loadA(0);
    stageB(0, 0);

    for (int c = 0; c < 4; c++) {
        const int cur = c & 1;
        stageA(cur);
        if (c + 1 < 4) {
            loadA(c + 1);
            stageB(c + 1, cur ^ 1);
            CP_WAIT(1);
        } else {
            CP_WAIT(0);
        }
        __syncthreads();

        const uint32_t* sAh = dyn + cur * BUF_U;
        const uint32_t* sAl = sAh + OA_LO;
        const uint32_t* sBh = dyn + cur * BUF_U + OB_HI;
        const uint32_t* sBl = dyn + cur * BUF_U + OB_LO;

#pragma unroll
        for (int s = 0; s < 2; s++) {
            const int kc = s * 8 + gc;
            uint32_t ah[2][4], al[2][4];
#pragma unroll
            for (int mt = 0; mt < 2; mt++) {
                int r = warp_m * 32 + mt * 16 + gr;
                ah[mt][0] = sAh[r * PADU + kc];
                ah[mt][1] = sAh[(r + 8) * PADU + kc];
                ah[mt][2] = sAh[r * PADU + kc + 4];
                ah[mt][3] = sAh[(r + 8) * PADU + kc + 4];
                al[mt][0] = sAl[r * PADU + kc];
                al[mt][1] = sAl[(r + 8) * PADU + kc];
                al[mt][2] = sAl[r * PADU + kc + 4];
                al[mt][3] = sAl[(r + 8) * PADU + kc + 4];
            }
#pragma unroll
            for (int nt = 0; nt < NT; nt++) {
                int n = warp_n * (NN / 2) + nt * 8 + gr;
                uint32_t bh[2], bl[2];
                bh[0] = sBh[n * PADU + kc];
                bh[1] = sBh[n * PADU + kc + 4];
                bl[0] = sBl[n * PADU + kc];
                bl[1] = sBl[n * PADU + kc + 4];
#pragma unroll
                for (int mt = 0; mt < 2; mt++) {
                    mma16816(acc[mt][nt], ah[mt], bh);
                    mma16816(acc[mt][nt], ah[mt], bl);
                    mma16816(acc[mt][nt], al[mt], bh);
                }
            }
        }
        __syncthreads();
    }

#pragma unroll
    for (int mt = 0; mt < 2; mt++) {
#pragma unroll
        for (int nt = 0; nt < NT; nt++) {
            int col = warp_n * (NN / 2) + nt * 8 + 2 * gc;
            float b0 = __ldg(bias + col);
            float b1 = __ldg(bias + col + 1);
#pragma unroll
            for (int half = 0; half < 2; half++) {
                int r = m0 + warp_m * 32 + mt * 16 + gr + half * 8;
                if (r >= M) continue;
                float ox = fmaxf(acc[mt][nt][2 * half + 0] + b0, 0.f);
                float oy = fmaxf(acc[mt][nt][2 * half + 1] + b1, 0.f);
                float hx, lx, hy, ly;
                hilo(ox, hx, lx);
                hilo(oy, hy, ly);
                Chi[(size_t)r * 64 + col / 2] = pack2(hx, hy);
                Clo[(size_t)r * 64 + col / 2] = pack2(lx, ly);
            }
        }
    }
}

// ================= fused aggregation: half-warp per node (fp16 h), node-range version =================
__global__ void gather_kernel(const uint32_t* __restrict__ hf,
                              uint32_t* __restrict__ cat_hi,
                              uint32_t* __restrict__ cat_lo,
                              int node_base, int node_count) {
    int t = blockIdx.x * blockDim.x + threadIdx.x;
    int idx = t >> 4;
    int sl = t & 15;
    if (idx >= node_count) return;
    int node = node_base + idx;

    int beg = g_off[node];
    int end = g_off[node + 1];
    float dinv = 1.0f / (float)(end - beg + 1);

    float acc[8];
    {
        uint4 sv = *(const uint4*)(hf + (size_t)node * 64 + sl * 4);
        float2 a0 = __half22float2(*(__half2*)&sv.x);
        float2 a1 = __half22float2(*(__half2*)&sv.y);
        float2 a2 = __half22float2(*(__half2*)&sv.z);
        float2 a3 = __half22float2(*(__half2*)&sv.w);
        acc[0] = a0.x * dinv; acc[1] = a0.y * dinv;
        acc[2] = a1.x * dinv; acc[3] = a1.y * dinv;
        acc[4] = a2.x * dinv; acc[5] = a2.y * dinv;
        acc[6] = a3.x * dinv; acc[7] = a3.y * dinv;
    }

#define ACCUM(vv, nm) do { \
        float2 _a = __half22float2(*(__half2*)&(vv).x); \
        float2 _b = __half22float2(*(__half2*)&(vv).y); \
        float2 _c = __half22float2(*(__half2*)&(vv).z); \
        float2 _d = __half22float2(*(__half2*)&(vv).w); \
        acc[0] += _a.x * (nm); acc[1] += _a.y * (nm); \
        acc[2] += _b.x * (nm); acc[3] += _b.y * (nm); \
        acc[4] += _c.x * (nm); acc[5] += _c.y * (nm); \
        acc[6] += _d.x * (nm); acc[7] += _d.y * (nm); } while (0)

    int i = beg;
    for (; i + 4 <= end; i += 4) {
        float2 p0 = __ldcs(&g_adj[i + 0]);
        float2 p1 = __ldcs(&g_adj[i + 1]);
        float2 p2 = __ldcs(&g_adj[i + 2]);
        float2 p3 = __ldcs(&g_adj[i + 3]);
        uint4 v0 = *(const uint4*)(hf + (size_t)__float_as_int(p0.x) * 64 + sl * 4);
        uint4 v1 = *(const uint4*)(hf + (size_t)__float_as_int(p1.x) * 64 + sl * 4);
        uint4 v2 = *(const uint4*)(hf + (size_t)__float_as_int(p2.x) * 64 + sl * 4);
        uint4 v3 = *(const uint4*)(hf + (size_t)__float_as_int(p3.x) * 64 + sl * 4);
        ACCUM(v0, p0.y);
        ACCUM(v1, p1.y);
        ACCUM(v2, p2.y);
        ACCUM(v3, p3.y);
    }
    for (; i < end; i++) {
        float2 p = __ldcs(&g_adj[i]);
        uint4 v = *(const uint4*)(hf + (size_t)__float_as_int(p.x) * 64 + sl * 4);
        ACCUM(v, p.y);
    }
#undef ACCUM

    uint4 uhi, ulo;
    float hh, ll;
    float h2v[8], l2v[8];
#pragma unroll
    for (int j = 0; j < 8; j++) {
        float r = fmaxf(acc[j], 0.f);
        hilo(r, hh, ll);
        h2v[j] = hh;
        l2v[j] = ll;
    }
    uhi.x = pack2(h2v[0], h2v[1]); uhi.y = pack2(h2v[2], h2v[3]);
    uhi.z = pack2(h2v[4], h2v[5]); uhi.w = pack2(h2v[6], h2v[7]);
    ulo.x = pack2(l2v[0], l2v[1]); ulo.y = pack2(l2v[2], l2v[3]);
    ulo.z = pack2(l2v[4], l2v[5]); ulo.w = pack2(l2v[6], l2v[7]);
    *(uint4*)(cat_hi + (size_t)node * CATU + sl * 4) = uhi;
    *(uint4*)(cat_lo + (size_t)node * CATU + sl * 4) = ulo;
}

// ================= launch =================
extern "C" void kernel_launch(void* const* d_in, const int* in_sizes, int n_in,
                              void* d_out, int out_size) {
    const float* x     = (const float*)d_in[0];
    const void*  ei    = d_in[1];
    const float* W_in  = (const float*)d_in[2];
    const float* b_in  = (const float*)d_in[3];
    const float* Wc    = (const float*)d_in[4];
    const float* bc    = (const float*)d_in[5];
    const float* W_out = (const float*)d_in[6];
    const float* b_out = (const float*)d_in[7];
    float* out = (float*)d_out;

    uint32_t *x0h, *x0l, *hf, *cath, *catl, *wh, *wl;
    cudaGetSymbolAddress((void**)&hf, g_hf);
    cudaGetSymbolAddress((void**)&x0h, g_x0h);
    cudaGetSymbolAddress((void**)&x0l, g_x0l);
    cudaGetSymbolAddress((void**)&cath, g_cath);
    cudaGetSymbolAddress((void**)&catl, g_catl);
    cudaGetSymbolAddress((void**)&wh, g_wh);
    cudaGetSymbolAddress((void**)&wl, g_wl);

    const int SM128 = 2 * (2 * 128 * PADU + 2 * 128 * PADU) * 4;   // 81920
    const int SM64  = 2 * (2 * 128 * PADU + 2 * 64 * PADU) * 4;    // 61440
    cudaFuncSetAttribute((const void*)mma_gemm_pipe<128, 1>, cudaFuncAttributeMaxDynamicSharedMemorySize, SM128);
    cudaFuncSetAttribute((const void*)mma_gemm_pipe<64, 0>,  cudaFuncAttributeMaxDynamicSharedMemorySize, SM64);
    cudaFuncSetAttribute((const void*)mma_gemm_inproj,       cudaFuncAttributeMaxDynamicSharedMemorySize, SM128);

    // fork/join resources — created once on the first (uncaptured) correctness call
    static cudaStream_t s2 = nullptr;
    static cudaEvent_t e1 = nullptr, e2 = nullptr, efin = nullptr;
    static cudaEvent_t eA[N_LAYERS], eB[N_LAYERS], eGm[N_LAYERS];
    if (!s2) {
        cudaStreamCreateWithFlags(&s2, cudaStreamNonBlocking);
        cudaEventCreateWithFlags(&e1, cudaEventDisableTiming);
        cudaEventCreateWithFlags(&e2, cudaEventDisableTiming);
        cudaEventCreateWithFlags(&efin, cudaEventDisableTiming);
        for (int i = 0; i < N_LAYERS; i++) {
            cudaEventCreateWithFlags(&eA[i], cudaEventDisableTiming);
            cudaEventCreateWithFlags(&eB[i], cudaEventDisableTiming);
            cudaEventCreateWithFlags(&eGm[i], cudaEventDisableTiming);
        }
    }

    const int TB = 256;
    const int M = N_NODES;
    const int GB = TILES;                 // 391
    const int H0_TILES = HALF_TILES;      // 196
    const int H1_TILES = TILES - HALF_TILES;  // 195
    const int H0_NODES = HALF_NODES;      // 25088
    const int H1_NODES = N_NODES - HALF_NODES;

    const int gBlk0 = (H0_NODES * 16 + TB - 1) / TB;
    const int gBlk1 = (H1_NODES * 16 + TB - 1) / TB;

    // ---- stream 0: shared init ----
    fused_init_kernel<<<(WU_TOT + TB - 1) / TB, TB>>>(ei, W_in, Wc, W_out);
    cudaEventRecord(e1, 0);

    // ---- branch s2: CSR build (hidden under inproj + GEMM L0) ----
    cudaStreamWaitEvent(s2, e1, 0);
    degcount_kernel<<<(N_EDGES + TB - 1) / TB, TB, 0, s2>>>(ei);
    scan1_kernel<<<NBLK, SCAN_B, 0, s2>>>();
    scan2_kernel<<<1, SCAN_B, 0, s2>>>();
    scan3_kernel<<<NBLK, SCAN_B, 0, s2>>>();
    fill_kernel<<<(N_EDGES + TB - 1) / TB, TB, 0, s2>>>(ei);
    cudaEventRecord(e2, s2);

    // ---- stream 0 (concurrent): input projection + layer-0 GEMM (full) ----
    mma_gemm_inproj<<<GB, 256, SM128>>>(x, wh + WU_IN, wl + WU_IN, b_in, x0h, x0l, M);
    mma_gemm_pipe<128, 1><<<GB, 256, SM128>>>(
        x0h, x0l, 64,
        wh + WU_C, wl + WU_C, 64, bc,
        nullptr, 0, hf, 64, M, HID, 0);

    // ---- join: gather L0 needs the CSR ----
    cudaStreamWaitEvent(0, e2, 0);

    // ---- layers with row-split software pipeline ----
    for (int L = 0; L < N_LAYERS; L++) {
        if (L > 0) cudaStreamWaitEvent(0, eGm[L], 0);   // gather L needs full hf from GEMM L (on s2)

        gather_kernel<<<gBlk0, TB>>>(hf, cath + (size_t)L * 64, catl + (size_t)L * 64, 0, H0_NODES);
        cudaEventRecord(eA[L], 0);
        gather_kernel<<<gBlk1, TB>>>(hf, cath + (size_t)L * 64, catl + (size_t)L * 64, H0_NODES, H1_NODES);
        cudaEventRecord(eB[L], 0);

        if (L < N_LAYERS - 1) {
            // GEMM L+1 row-halves on s2, overlapping gather half1 on s0
            cudaStreamWaitEvent(s2, eA[L], 0);
            mma_gemm_pipe<128, 1><<<H0_TILES, 256, SM128, s2>>>(
                cath + (size_t)L * 64, catl + (size_t)L * 64, CATU,
                wh + WU_C + (size_t)(L + 1) * 8192, wl + WU_C + (size_t)(L + 1) * 8192, 64,
                bc + (size_t)(L + 1) * HID,
                nullptr, 0, hf, 64, M, HID, 0);
            cudaStreamWaitEvent(s2, eB[L], 0);
            mma_gemm_pipe<128, 1><<<H1_TILES, 256, SM128, s2>>>(
                cath + (size_t)L * 64, catl + (size_t)L * 64, CATU,
                wh + WU_C + (size_t)(L + 1) * 8192, wl + WU_C + (size_t)(L + 1) * 8192, 64,
                bc + (size_t)(L + 1) * HID,
                nullptr, 0, hf, 64, M, HID, HALF_TILES);
            cudaEventRecord(eGm[L + 1], s2);
        } else {
            // final projection (K=512) row-halves on s2, first half overlaps gather L3 half1
            cudaStreamWaitEvent(s2, eA[L], 0);
            mma_gemm_pipe<64, 0><<<H0_TILES, 256, SM64, s2>>>(
                cath, catl, CATU,
                wh + WU_OUT, wl + WU_OUT, 256,
                b_out,
                out, OUT_CH, nullptr, 0, M, CATW, 0);
            cudaStreamWaitEvent(s2, eB[L], 0);
            mma_gemm_pipe<64, 0><<<H1_TILES, 256, SM64, s2>>>(
                cath, catl, CATU,
                wh + WU_OUT, wl + WU_OUT, 256,
                b_out,
                out, OUT_CH, nullptr, 0, M, CATW, HALF_TILES);
            cudaEventRecord(efin, s2);
        }
    }

    // ---- join everything back to stream 0 before capture ends ----
    cudaStreamWaitEvent(0, efin, 0);
}

// round 15
// speedup vs baseline: 1.2028x; 1.2028x over previous
#include <cuda_runtime.h>
#include <cuda_bf16.h>
#include <cuda_fp16.h>
#include <math.h>
#include <stdint.h>

#define N_NODES 50000
#define N_EDGES 800000
#define HID     128
#define OUT_CH  64
#define N_LAYERS 4
#define CATW    (HID * N_LAYERS)   // 512
#define CATU    (CATW / 2)         // 256 u32 per row

// weight regions in split-u32 space
#define WU_IN   0
#define WU_C    8192
#define WU_OUT  (WU_C + 4 * 8192)
#define WU_TOT  (WU_OUT + 16384)   // 57344

// ================= device scratch =================
__device__ __align__(16) uint32_t g_x0h[(size_t)N_NODES * HID / 2];
__device__ __align__(16) uint32_t g_x0l[(size_t)N_NODES * HID / 2];
__device__ __align__(16) uint32_t g_hf[(size_t)N_NODES * HID / 2];   // h as half2
__device__ __align__(16) uint32_t g_cath[(size_t)N_NODES * CATU];
__device__ __align__(16) uint32_t g_catl[(size_t)N_NODES * CATU];
__device__ __align__(16) uint32_t g_wh[WU_TOT];
__device__ __align__(16) uint32_t g_wl[WU_TOT];
__device__ int    g_degi[N_NODES];
__device__ int    g_off[N_NODES + 1];
__device__ int    g_cur[N_NODES];
__device__ float2 g_adj[N_EDGES];
__device__ int    g_is64;

#define SCAN_B 256
#define NBLK ((N_NODES + SCAN_B - 1) / SCAN_B)   // 196
__device__ int g_bsum[NBLK];

// ================= helpers =================
__device__ __forceinline__ uint32_t pack2(float lo_elem, float hi_elem) {
    __nv_bfloat162 t = __floats2bfloat162_rn(lo_elem, hi_elem);
    return *(uint32_t*)&t;
}
__device__ __forceinline__ void hilo(float x, float& h, float& l) {
    float hf = __bfloat162float(__float2bfloat16_rn(x));
    h = hf;
    l = x - hf;
}
__device__ __forceinline__ void mma16816(float* c, const uint32_t* a, const uint32_t* b) {
    asm volatile(
        "mma.sync.aligned.m16n8k16.row.col.f32.bf16.bf16.f32 "
        "{%0,%1,%2,%3}, {%4,%5,%6,%7}, {%8,%9}, {%0,%1,%2,%3};"
        : "+f"(c[0]), "+f"(c[1]), "+f"(c[2]), "+f"(c[3])
        : "r"(a[0]), "r"(a[1]), "r"(a[2]), "r"(a[3]), "r"(b[0]), "r"(b[1]));
}
__device__ __forceinline__ uint32_t smem_u32(const void* p) {
    uint32_t a;
    asm("{ .reg .u64 t; cvta.to.shared.u64 t, %1; cvt.u32.u64 %0, t; }" : "=r"(a) : "l"(p));
    return a;
}
__device__ __forceinline__ void cp_async16(uint32_t saddr, const void* gptr, bool pred) {
    int sz = pred ? 16 : 0;
    asm volatile("cp.async.cg.shared.global [%0], [%1], 16, %2;"
                 :: "r"(saddr), "l"(gptr), "r"(sz));
}
#define CP_COMMIT() asm volatile("cp.async.commit_group;" ::: "memory")
#define CP_WAIT(n)  asm volatile("cp.async.wait_group %0;" :: "n"(n) : "memory")

// ================= fused init: degree=1 + weight split + dtype detect =================
__global__ void fused_init_kernel(const void* ei,
                                  const float* __restrict__ W_in,
                                  const float* __restrict__ Wc,
                                  const float* __restrict__ W_out) {
    int t = blockIdx.x * blockDim.x + threadIdx.x;
    if (t < N_NODES) g_degi[t] = 1;
    if (t < WU_TOT) {
        const float* src;
        int rt;
        if (t < WU_C) { src = W_in; rt = t; }
        else if (t < WU_OUT) { src = Wc; rt = t - WU_C; }
        else { src = W_out; rt = t - WU_OUT; }
        float a = src[2 * rt], b = src[2 * rt + 1];
        float ha, la, hb, lb;
        hilo(a, ha, la);
        hilo(b, hb, lb);
        g_wh[t] = pack2(ha, hb);
        g_wl[t] = pack2(la, lb);
    }
    if (blockIdx.x == 0) {
        const long long* p = (const long long*)ei;
        int bad = 0;
        for (int i = threadIdx.x; i < 1024; i += blockDim.x) {
            long long v = p[i];
            if (v < 0 || v >= (long long)N_NODES) bad = 1;
        }
        bad = __syncthreads_or(bad);
        if (threadIdx.x == 0) g_is64 = bad ? 0 : 1;
    }
}

__global__ void degcount_kernel(const void* ei) {
    int e = blockIdx.x * blockDim.x + threadIdx.x;
    if (e >= N_EDGES) return;
    int d;
    if (g_is64) d = (int)((const long long*)ei)[N_EDGES + e];
    else        d = ((const int*)ei)[N_EDGES + e];
    atomicAdd(&g_degi[d], 1);
}

// ================= proven 3-phase scan =================
__global__ void scan1_kernel() {
    __shared__ int s[SCAN_B];
    int t = threadIdx.x;
    int v = blockIdx.x * SCAN_B + t;
    s[t] = (v < N_NODES) ? (g_degi[v] - 1) : 0;
    __syncthreads();
    for (int off = SCAN_B / 2; off > 0; off >>= 1) {
        if (t < off) s[t] += s[t + off];
        __syncthreads();
    }
    if (t == 0) g_bsum[blockIdx.x] = s[0];
}
__global__ void scan2_kernel() {
    __shared__ int s[SCAN_B];
    int t = threadIdx.x;
    int v = (t < NBLK) ? g_bsum[t] : 0;
    s[t] = v;
    __syncthreads();
    for (int off = 1; off < SCAN_B; off <<= 1) {
        int a = (t >= off) ? s[t - off] : 0;
        __syncthreads();
        s[t] += a;
        __syncthreads();
    }
    if (t < NBLK) g_bsum[t] = s[t] - v;
    if (t == NBLK - 1) g_off[N_NODES] = s[t];
}
__global__ void scan3_kernel() {
    __shared__ int s[SCAN_B];
    int t = threadIdx.x;
    int v = blockIdx.x * SCAN_B + t;
    int d = (v < N_NODES) ? (g_degi[v] - 1) : 0;
    s[t] = d;
    __syncthreads();
    for (int off = 1; off < SCAN_B; off <<= 1) {
        int a = (t >= off) ? s[t - off] : 0;
        __syncthreads();
        s[t] += a;
        __syncthreads();
    }
    if (v < N_NODES) {
        g_off[v] = g_bsum[blockIdx.x] + s[t] - d;
        g_cur[v] = 0;
    }
}
__global__ void fill_kernel(const void* ei) {
    int e = blockIdx.x * blockDim.x + threadIdx.x;
    if (e >= N_EDGES) return;
    int s, d;
    if (g_is64) {
        const long long* p = (const long long*)ei;
        s = (int)p[e];
        d = (int)p[N_EDGES + e];
    } else {
        const int* p = (const int*)ei;
        s = p[e];
        d = p[N_EDGES + e];
    }
    int pos = g_off[d] + atomicAdd(&g_cur[d], 1);
    float nm = rsqrtf((float)g_degi[s] * (float)g_degi[d]);
    g_adj[pos] = make_float2(__int_as_float(s), nm);
}

// ================= pipelined bf16x2-split GEMM (BM=128, cp.async double buffer) =================
// EPI: 0 -> fp32 store (bias), 1 -> fp16 half2 store (h for gather)
#define PADU 20

template <int NN, int EPI>
__global__ void __launch_bounds__(256) mma_gemm_pipe(
    const uint32_t* __restrict__ Ah, const uint32_t* __restrict__ Al, int lda_u,
    const uint32_t* __restrict__ Bh, const uint32_t* __restrict__ Bl, int ldb_u,
    const float* __restrict__ bias,
    float* __restrict__ Cf, int ldc,
    uint32_t* __restrict__ Ch, int ldh_u,
    int M, int K)
{
    extern __shared__ uint32_t dyn[];
    constexpr int OA_LO = 128 * PADU;
    constexpr int OB_HI = 2 * 128 * PADU;
    constexpr int OB_LO = OB_HI + NN * PADU;
    constexpr int BUF_U = OB_LO + NN * PADU;

    const int tid = threadIdx.x;
    const int wid = tid >> 5;
    const int lane = tid & 31;
    const int gr = lane >> 2;
    const int gc = lane & 3;
    const int warp_m = wid >> 1;
    const int warp_n = wid & 1;
    const int m0 = blockIdx.x * 128;
    constexpr int NT = NN / 16;

    const uint32_t sbase = smem_u32(dyn);
    const int chunks = K >> 5;

    float acc[2][NT][4];
#pragma unroll
    for (int mt = 0; mt < 2; mt++)
#pragma unroll
        for (int nt = 0; nt < NT; nt++)
#pragma unroll
            for (int j = 0; j < 4; j++) acc[mt][nt][j] = 0.0f;

    auto stage = [&](int c, int buf) {
        const int k0u = c << 4;
        const uint32_t sb = sbase + (uint32_t)buf * BUF_U * 4;
#pragma unroll
        for (int it = 0; it < 2; it++) {
            int idx = tid + it * 256;
            int row = idx >> 2, j = idx & 3;
            bool ok = (m0 + row < M);
            size_t go = ok ? ((size_t)(m0 + row) * lda_u + k0u + j * 4) : 0;
            uint32_t so = (uint32_t)(row * PADU + j * 4) * 4;
            cp_async16(sb + so, Ah + go, ok);
            cp_async16(sb + OA_LO * 4 + so, Al + go, ok);
        }
#pragma unroll
        for (int it = 0; it < NN / 64; it++) {
            int idx = tid + it * 256;
            int row = idx >> 2, j = idx & 3;
            size_t go = (size_t)row * ldb_u + k0u + j * 4;
            uint32_t so = (uint32_t)(row * PADU + j * 4) * 4;
            cp_async16(sb + OB_HI * 4 + so, Bh + go, true);
            cp_async16(sb + OB_LO * 4 + so, Bl + go, true);
        }
        CP_COMMIT();
    };

    stage(0, 0);

    for (int c = 0; c < chunks; c++) {
        const int cur = c & 1;
        if (c + 1 < chunks) {
            stage(c + 1, cur ^ 1);
            CP_WAIT(1);
        } else {
            CP_WAIT(0);
        }
        __syncthreads();

        const uint32_t* sAh = dyn + cur * BUF_U;
        const uint32_t* sAl = sAh + OA_LO;
        const uint32_t* sBh = dyn + cur * BUF_U + OB_HI;
        const uint32_t* sBl = dyn + cur * BUF_U + OB_LO;

#pragma unroll
        for (int s = 0; s < 2; s++) {
            const int kc = s * 8 + gc;
            uint32_t ah[2][4], al[2][4];
#pragma unroll
            for (int mt = 0; mt < 2; mt++) {
                int r = warp_m * 32 + mt * 16 + gr;
                ah[mt][0] = sAh[r * PADU + kc];
                ah[mt][1] = sAh[(r + 8) * PADU + kc];
                ah[mt][2] = sAh[r * PADU + kc + 4];
                ah[mt][3] = sAh[(r + 8) * PADU + kc + 4];
                al[mt][0] = sAl[r * PADU + kc];
                al[mt][1] = sAl[(r + 8) * PADU + kc];
                al[mt][2] = sAl[r * PADU + kc + 4];
                al[mt][3] = sAl[(r + 8) * PADU + kc + 4];
            }
#pragma unroll
            for (int nt = 0; nt < NT; nt++) {
                int n = warp_n * (NN / 2) + nt * 8 + gr;
                uint32_t bh[2], bl[2];
                bh[0] = sBh[n * PADU + kc];
                bh[1] = sBh[n * PADU + kc + 4];
                bl[0] = sBl[n * PADU + kc];
                bl[1] = sBl[n * PADU + kc + 4];
#pragma unroll
                for (int mt = 0; mt < 2; mt++) {
                    mma16816(acc[mt][nt], ah[mt], bh);
                    mma16816(acc[mt][nt], ah[mt], bl);
                    mma16816(acc[mt][nt], al[mt], bh);
                }
            }
        }
        __syncthreads();
    }

#pragma unroll
    for (int mt = 0; mt < 2; mt++) {
#pragma unroll
        for (int nt = 0; nt < NT; nt++) {
            int col = warp_n * (NN / 2) + nt * 8 + 2 * gc;
            float b0 = __ldg(bias + col);
            float b1 = __ldg(bias + col + 1);
#pragma unroll
            for (int half = 0; half < 2; half++) {
                int r = m0 + warp_m * 32 + mt * 16 + gr + half * 8;
                if (r >= M) continue;
                float ox = acc[mt][nt][2 * half + 0] + b0;
                float oy = acc[mt][nt][2 * half + 1] + b1;
                if (EPI == 1) {
                    __half2 p = __floats2half2_rn(ox, oy);
                    Ch[(size_t)r * ldh_u + col / 2] = *(uint32_t*)&p;
                } else {
                    *(float2*)(Cf + (size_t)r * ldc + col) = make_float2(ox, oy);
                }
            }
        }
    }
}

// ================= input-projection GEMM: pipelined (reg-prefetch A, cp.async B) =================
__global__ void __launch_bounds__(256) mma_gemm_inproj(
    const float* __restrict__ A,
    const uint32_t* __restrict__ Bh, const uint32_t* __restrict__ Bl,
    const float* __restrict__ bias,
    uint32_t* __restrict__ Chi, uint32_t* __restrict__ Clo,
    int M)
{
    constexpr int NN = 128;
    constexpr int K = 128;
    extern __shared__ uint32_t dyn[];
    constexpr int OA_LO = 128 * PADU;
    constexpr int OB_HI = 2 * 128 * PADU;
    constexpr int OB_LO = OB_HI + NN * PADU;
    constexpr int BUF_U = OB_LO + NN * PADU;

    const int tid = threadIdx.x;
    const int wid = tid >> 5;
    const int lane = tid & 31;
    const int gr = lane >> 2;
    const int gc = lane & 3;
    const int warp_m = wid >> 1;
    const int warp_n = wid & 1;
    const int m0 = blockIdx.x * 128;
    constexpr int NT = NN / 16;

    const uint32_t sbase = smem_u32(dyn);

    float acc[2][NT][4];
#pragma unroll
    for (int mt = 0; mt < 2; mt++)
#pragma unroll
        for (int nt = 0; nt < NT; nt++)
#pragma unroll
            for (int j = 0; j < 4; j++) acc[mt][nt][j] = 0.0f;

    const int arow = tid >> 1;
    const int aq = (tid & 1) * 4;
    float4 pa[4];
    auto loadA = [&](int c) {
        bool ok = (m0 + arow < M);
        const float* base = A + (size_t)(m0 + arow) * K + c * 32 + aq * 4;
#pragma unroll
        for (int j = 0; j < 4; j++)
            pa[j] = ok ? *(const float4*)(base + j * 4) : make_float4(0, 0, 0, 0);
    };
    auto stageA = [&](int buf) {
        uint32_t* sA = dyn + buf * BUF_U;
        uint32_t* sAlo = sA + OA_LO;
#pragma unroll
        for (int j = 0; j < 4; j++) {
            float h0, h1, h2, h3, l0, l1, l2, l3;
            hilo(pa[j].x, h0, l0); hilo(pa[j].y, h1, l1);
            hilo(pa[j].z, h2, l2); hilo(pa[j].w, h3, l3);
            int base = arow * PADU + 2 * (aq + j);
            sA[base + 0] = pack2(h0, h1);
            sA[base + 1] = pack2(h2, h3);
            sAlo[base + 0] = pack2(l0, l1);
            sAlo[base + 1] = pack2(l2, l3);
        }
    };
    auto stageB = [&](int c, int buf) {
        const int k0u = c << 4;
        const uint32_t sb = sbase + (uint32_t)buf * BUF_U * 4;
#pragma unroll
        for (int it = 0; it < 2; it++) {
            int idx = tid + it * 256;
            int row = idx >> 2, j = idx & 3;
            size_t go = (size_t)row * 64 + k0u + j * 4;
            uint32_t so = (uint32_t)(row * PADU + j * 4) * 4;
            cp_async16(sb + OB_HI * 4 + so, Bh + go, true);
            cp_async16(sb + OB_LO * 4 + so, Bl + go, true);
        }
        CP_COMMIT();
    };

    loadA(0);
    stageB(0, 0);

    for (int c = 0; c < 4; c++) {
        const int cur = c & 1;
        stageA(cur);
        if (c + 1 < 4) {
            loadA(c + 1);
            stageB(c + 1, cur ^ 1);
            CP_WAIT(1);
        } else {
            CP_WAIT(0);
        }
        __syncthreads();

        const uint32_t* sAh = dyn + cur * BUF_U;
        const uint32_t* sAl = sAh + OA_LO;
        const uint32_t* sBh = dyn + cur * BUF_U + OB_HI;
        const uint32_t* sBl = dyn + cur * BUF_U + OB_LO;

#pragma unroll
        for (int s = 0; s < 2; s++) {
            const int kc = s * 8 + gc;
            uint32_t ah[2][4], al[2][4];
#pragma unroll
            for (int mt = 0; mt < 2; mt++) {
                int r = warp_m * 32 + mt * 16 + gr;
                ah[mt][0] = sAh[r * PADU + kc];
                ah[mt][1] = sAh[(r + 8) * PADU + kc];
                ah[mt][2] = sAh[r * PADU + kc + 4];
                ah[mt][3] = sAh[(r + 8) * PADU + kc + 4];
                al[mt][0] = sAl[r * PADU + kc];
                al[mt][1] = sAl[(r + 8) * PADU + kc];
                al[mt][2] = sAl[r * PADU + kc + 4];
                al[mt][3] = sAl[(r + 8) * PADU + kc + 4];
            }
#pragma unroll
            for (int nt = 0; nt < NT; nt++) {
                int n = warp_n * (NN / 2) + nt * 8 + gr;
                uint32_t bh[2], bl[2];
                bh[0] = sBh[n * PADU + kc];
                bh[1] = sBh[n * PADU + kc + 4];
                bl[0] = sBl[n * PADU + kc];
                bl[1] = sBl[n * PADU + kc + 4];
#pragma unroll
                for (int mt = 0; mt < 2; mt++) {
                    mma16816(acc[mt][nt], ah[mt], bh);
                    mma16816(acc[mt][nt], ah[mt], bl);
                    mma16816(acc[mt][nt], al[mt], bh);
                }
            }
        }
        __syncthreads();
    }

#pragma unroll
    for (int mt = 0; mt < 2; mt++) {
#pragma unroll
        for (int nt = 0; nt < NT; nt++) {
            int col = warp_n * (NN / 2) + nt * 8 + 2 * gc;
            float b0 = __ldg(bias + col);
            float b1 = __ldg(bias + col + 1);
#pragma unroll
            for (int half = 0; half < 2; half++) {
                int r = m0 + warp_m * 32 + mt * 16 + gr + half * 8;
                if (r >= M) continue;
                float ox = fmaxf(acc[mt][nt][2 * half + 0] + b0, 0.f);
                float oy = fmaxf(acc[mt][nt][2 * half + 1] + b1, 0.f);
                float hx, lx, hy, ly;
                hilo(ox, hx, lx);
                hilo(oy, hy, ly);
                Chi[(size_t)r * 64 + col / 2] = pack2(hx, hy);
                Clo[(size_t)r * 64 + col / 2] = pack2(lx, ly);
            }
        }
    }
}

// ================= fused aggregation: half-warp per node (fp16 h) =================
__global__ void gather_kernel(const uint32_t* __restrict__ hf,
                              uint32_t* __restrict__ cat_hi,
                              uint32_t* __restrict__ cat_lo) {
    int t = blockIdx.x * blockDim.x + threadIdx.x;
    int node = t >> 4;
    int sl = t & 15;
    if (node >= N_NODES) return;

    int beg = g_off[node];
    int end = g_off[node + 1];
    float dinv = 1.0f / (float)(end - beg + 1);

    float acc[8];
    {
        uint4 sv = *(const uint4*)(hf + (size_t)node * 64 + sl * 4);
        float2 a0 = __half22float2(*(__half2*)&sv.x);
        float2 a1 = __half22float2(*(__half2*)&sv.y);
        float2 a2 = __half22float2(*(__half2*)&sv.z);
        float2 a3 = __half22float2(*(__half2*)&sv.w);
        acc[0] = a0.x * dinv; acc[1] = a0.y * dinv;
        acc[2] = a1.x * dinv; acc[3] = a1.y * dinv;
        acc[4] = a2.x * dinv; acc[5] = a2.y * dinv;
        acc[6] = a3.x * dinv; acc[7] = a3.y * dinv;
    }

#define ACCUM(vv, nm) do { \
        float2 _a = __half22float2(*(__half2*)&(vv).x); \
        float2 _b = __half22float2(*(__half2*)&(vv).y); \
        float2 _c = __half22float2(*(__half2*)&(vv).z); \
        float2 _d = __half22float2(*(__half2*)&(vv).w); \
        acc[0] += _a.x * (nm); acc[1] += _a.y * (nm); \
        acc[2] += _b.x * (nm); acc[3] += _b.y * (nm); \
        acc[4] += _c.x * (nm); acc[5] += _c.y * (nm); \
        acc[6] += _d.x * (nm); acc[7] += _d.y * (nm); } while (0)

    int i = beg;
    for (; i + 4 <= end; i += 4) {
        float2 p0 = __ldcs(&g_adj[i + 0]);
        float2 p1 = __ldcs(&g_adj[i + 1]);
        float2 p2 = __ldcs(&g_adj[i + 2]);
        float2 p3 = __ldcs(&g_adj[i + 3]);
        uint4 v0 = *(const uint4*)(hf + (size_t)__float_as_int(p0.x) * 64 + sl * 4);
        uint4 v1 = *(const uint4*)(hf + (size_t)__float_as_int(p1.x) * 64 + sl * 4);
        uint4 v2 = *(const uint4*)(hf + (size_t)__float_as_int(p2.x) * 64 + sl * 4);
        uint4 v3 = *(const uint4*)(hf + (size_t)__float_as_int(p3.x) * 64 + sl * 4);
        ACCUM(v0, p0.y);
        ACCUM(v1, p1.y);
        ACCUM(v2, p2.y);
        ACCUM(v3, p3.y);
    }
    for (; i < end; i++) {
        float2 p = __ldcs(&g_adj[i]);
        uint4 v = *(const uint4*)(hf + (size_t)__float_as_int(p.x) * 64 + sl * 4);
        ACCUM(v, p.y);
    }
#undef ACCUM

    uint4 uhi, ulo;
    float hh, ll;
    float h2v[8], l2v[8];
#pragma unroll
    for (int j = 0; j < 8; j++) {
        float r = fmaxf(acc[j], 0.f);
        hilo(r, hh, ll);
        h2v[j] = hh;
        l2v[j] = ll;
    }
    uhi.x = pack2(h2v[0], h2v[1]); uhi.y = pack2(h2v[2], h2v[3]);
    uhi.z = pack2(h2v[4], h2v[5]); uhi.w = pack2(h2v[6], h2v[7]);
    ulo.x = pack2(l2v[0], l2v[1]); ulo.y = pack2(l2v[2], l2v[3]);
    ulo.z = pack2(l2v[4], l2v[5]); ulo.w = pack2(l2v[6], l2v[7]);
    *(uint4*)(cat_hi + (size_t)node * CATU + sl * 4) = uhi;
    *(uint4*)(cat_lo + (size_t)node * CATU + sl * 4) = ulo;
}

// ================= launch =================
extern "C" void kernel_launch(void* const* d_in, const int* in_sizes, int n_in,
                              void* d_out, int out_size) {
    const float* x     = (const float*)d_in[0];
    const void*  ei    = d_in[1];
    const float* W_in  = (const float*)d_in[2];
    const float* b_in  = (const float*)d_in[3];
    const float* Wc    = (const float*)d_in[4];
    const float* bc    = (const float*)d_in[5];
    const float* W_out = (const float*)d_in[6];
    const float* b_out = (const float*)d_in[7];
    float* out = (float*)d_out;

    uint32_t *x0h, *x0l, *hf, *cath, *catl, *wh, *wl;
    cudaGetSymbolAddress((void**)&hf, g_hf);
    cudaGetSymbolAddress((void**)&x0h, g_x0h);
    cudaGetSymbolAddress((void**)&x0l, g_x0l);
    cudaGetSymbolAddress((void**)&cath, g_cath);
    cudaGetSymbolAddress((void**)&catl, g_catl);
    cudaGetSymbolAddress((void**)&wh, g_wh);
    cudaGetSymbolAddress((void**)&wl, g_wl);

    const int SM128 = 2 * (2 * 128 * PADU + 2 * 128 * PADU) * 4;   // 81920
    const int SM64  = 2 * (2 * 128 * PADU + 2 * 64 * PADU) * 4;    // 61440
    cudaFuncSetAttribute((const void*)mma_gemm_pipe<128, 1>, cudaFuncAttributeMaxDynamicSharedMemorySize, SM128);
    cudaFuncSetAttribute((const void*)mma_gemm_pipe<64, 0>,  cudaFuncAttributeMaxDynamicSharedMemorySize, SM64);
    cudaFuncSetAttribute((const void*)mma_gemm_inproj,       cudaFuncAttributeMaxDynamicSharedMemorySize, SM128);

    // fork/join resources — created once on the first (uncaptured) correctness call
    static cudaStream_t s2 = nullptr;
    static cudaEvent_t e1 = nullptr, e2 = nullptr;
    if (!s2) {
        cudaStreamCreateWithFlags(&s2, cudaStreamNonBlocking);
        cudaEventCreateWithFlags(&e1, cudaEventDisableTiming);
        cudaEventCreateWithFlags(&e2, cudaEventDisableTiming);
    }

    const int TB = 256;
    const int M = N_NODES;
    const int GB = (M + 127) / 128;   // 391

    // ---- stream 0: shared init ----
    fused_init_kernel<<<(WU_TOT + TB - 1) / TB, TB>>>(ei, W_in, Wc, W_out);
    cudaEventRecord(e1, 0);

    // ---- branch s2: CSR build (hidden under inproj + GEMM L0) ----
    cudaStreamWaitEvent(s2, e1, 0);
    degcount_kernel<<<(N_EDGES + TB - 1) / TB, TB, 0, s2>>>(ei);
    scan1_kernel<<<NBLK, SCAN_B, 0, s2>>>();
    scan2_kernel<<<1, SCAN_B, 0, s2>>>();
    scan3_kernel<<<NBLK, SCAN_B, 0, s2>>>();
    fill_kernel<<<(N_EDGES + TB - 1) / TB, TB, 0, s2>>>(ei);
    cudaEventRecord(e2, s2);

    // ---- stream 0 (concurrent): input projection + layer-0 GEMM ----
    mma_gemm_inproj<<<GB, 256, SM128>>>(x, wh + WU_IN, wl + WU_IN, b_in, x0h, x0l, M);
    mma_gemm_pipe<128, 1><<<GB, 256, SM128>>>(
        x0h, x0l, 64,
        wh + WU_C, wl + WU_C, 64, bc,
        nullptr, 0, hf, 64, M, HID);

    // ---- join: gather L0 needs the CSR ----
    cudaStreamWaitEvent(0, e2, 0);

    const int gthreads = N_NODES * 16;
    for (int L = 0; L < N_LAYERS; L++) {
        if (L > 0) {
            mma_gemm_pipe<128, 1><<<GB, 256, SM128>>>(
                cath + (size_t)(L - 1) * 64, catl + (size_t)(L - 1) * 64, CATU,
                wh + WU_C + (size_t)L * 8192, wl + WU_C + (size_t)L * 8192, 64,
                bc + (size_t)L * HID,
                nullptr, 0, hf, 64, M, HID);
        }
        gather_kernel<<<(gthreads + TB - 1) / TB, TB>>>(hf, cath + (size_t)L * 64, catl + (size_t)L * 64);
    }

    // ---- final projection: K=512, NN=64, fp32 out ----
    mma_gemm_pipe<64, 0><<<GB, 256, SM64>>>(
        cath, catl, CATU,
        wh + WU_OUT, wl + WU_OUT, 256,
        b_out,
        out, OUT_CH, nullptr, 0, M, CATW);
}

// round 16
// speedup vs baseline: 1.2611x; 1.0485x over previous
#include <cuda_runtime.h>
#include <cuda_bf16.h>
#include <cuda_fp16.h>
#include <math.h>
#include <stdint.h>

#define N_NODES 50000
#define N_EDGES 800000
#define HID     128
#define OUT_CH  64
#define N_LAYERS 4
#define CATW    (HID * N_LAYERS)   // 512
#define CATU    (CATW / 2)         // 256 u32 per row

// weight regions in split-u32 space
#define WU_IN   0
#define WU_C    8192
#define WU_OUT  (WU_C + 4 * 8192)
#define WU_TOT  (WU_OUT + 16384)   // 57344

// ================= device scratch =================
__device__ __align__(16) uint32_t g_x0h[(size_t)N_NODES * HID / 2];
__device__ __align__(16) uint32_t g_x0l[(size_t)N_NODES * HID / 2];
__device__ __align__(16) uint32_t g_hf[(size_t)N_NODES * HID / 2];   // h as half2
__device__ __align__(16) uint32_t g_cath[(size_t)N_NODES * CATU];
__device__ __align__(16) uint32_t g_catl[(size_t)N_NODES * CATU];
__device__ __align__(16) uint32_t g_wh[WU_TOT];
__device__ __align__(16) uint32_t g_wl[WU_TOT];
__device__ int    g_degi[N_NODES];
__device__ int    g_off[N_NODES + 1];
__device__ int    g_cur[N_NODES];
__device__ float2 g_adj[N_EDGES];
__device__ int    g_is64;

#define SCAN_B 256
#define NBLK ((N_NODES + SCAN_B - 1) / SCAN_B)   // 196
__device__ int g_bsum[NBLK];

// ================= helpers =================
__device__ __forceinline__ uint32_t pack2(float lo_elem, float hi_elem) {
    __nv_bfloat162 t = __floats2bfloat162_rn(lo_elem, hi_elem);
    return *(uint32_t*)&t;
}
__device__ __forceinline__ void hilo(float x, float& h, float& l) {
    float hf = __bfloat162float(__float2bfloat16_rn(x));
    h = hf;
    l = x - hf;
}
__device__ __forceinline__ void mma16816(float* c, const uint32_t* a, const uint32_t* b) {
    asm volatile(
        "mma.sync.aligned.m16n8k16.row.col.f32.bf16.bf16.f32 "
        "{%0,%1,%2,%3}, {%4,%5,%6,%7}, {%8,%9}, {%0,%1,%2,%3};"
        : "+f"(c[0]), "+f"(c[1]), "+f"(c[2]), "+f"(c[3])
        : "r"(a[0]), "r"(a[1]), "r"(a[2]), "r"(a[3]), "r"(b[0]), "r"(b[1]));
}
__device__ __forceinline__ uint32_t smem_u32(const void* p) {
    uint32_t a;
    asm("{ .reg .u64 t; cvta.to.shared.u64 t, %1; cvt.u32.u64 %0, t; }" : "=r"(a) : "l"(p));
    return a;
}
__device__ __forceinline__ void cp_async16(uint32_t saddr, const void* gptr, bool pred) {
    int sz = pred ? 16 : 0;
    asm volatile("cp.async.cg.shared.global [%0], [%1], 16, %2;"
                 :: "r"(saddr), "l"(gptr), "r"(sz));
}
#define CP_COMMIT() asm volatile("cp.async.commit_group;" ::: "memory")
#define CP_WAIT(n)  asm volatile("cp.async.wait_group %0;" :: "n"(n) : "memory")

// ================= fused init: degree=1 + weight split + dtype detect =================
__global__ void fused_init_kernel(const void* ei,
                                  const float* __restrict__ W_in,
                                  const float* __restrict__ Wc,
                                  const float* __restrict__ W_out) {
    int t = blockIdx.x * blockDim.x + threadIdx.x;
    if (t < N_NODES) g_degi[t] = 1;
    if (t < WU_TOT) {
        const float* src;
        int rt;
        if (t < WU_C) { src = W_in; rt = t; }
        else if (t < WU_OUT) { src = Wc; rt = t - WU_C; }
        else { src = W_out; rt = t - WU_OUT; }
        float a = src[2 * rt], b = src[2 * rt + 1];
        float ha, la, hb, lb;
        hilo(a, ha, la);
        hilo(b, hb, lb);
        g_wh[t] = pack2(ha, hb);
        g_wl[t] = pack2(la, lb);
    }
    if (blockIdx.x == 0) {
        const long long* p = (const long long*)ei;
        int bad = 0;
        for (int i = threadIdx.x; i < 1024; i += blockDim.x) {
            long long v = p[i];
            if (v < 0 || v >= (long long)N_NODES) bad = 1;
        }
        bad = __syncthreads_or(bad);
        if (threadIdx.x == 0) g_is64 = bad ? 0 : 1;
    }
}

__global__ void degcount_kernel(const void* ei) {
    int e = blockIdx.x * blockDim.x + threadIdx.x;
    if (e >= N_EDGES) return;
    int d;
    if (g_is64) d = (int)((const long long*)ei)[N_EDGES + e];
    else        d = ((const int*)ei)[N_EDGES + e];
    atomicAdd(&g_degi[d], 1);
}

// ================= proven 3-phase scan =================
__global__ void scan1_kernel() {
    __shared__ int s[SCAN_B];
    int t = threadIdx.x;
    int v = blockIdx.x * SCAN_B + t;
    s[t] = (v < N_NODES) ? (g_degi[v] - 1) : 0;
    __syncthreads();
    for (int off = SCAN_B / 2; off > 0; off >>= 1) {
        if (t < off) s[t] += s[t + off];
        __syncthreads();
    }
    if (t == 0) g_bsum[blockIdx.x] = s[0];
}
__global__ void scan2_kernel() {
    __shared__ int s[SCAN_B];
    int t = threadIdx.x;
    int v = (t < NBLK) ? g_bsum[t] : 0;
    s[t] = v;
    __syncthreads();
    for (int off = 1; off < SCAN_B; off <<= 1) {
        int a = (t >= off) ? s[t - off] : 0;
        __syncthreads();
        s[t] += a;
        __syncthreads();
    }
    if (t < NBLK) g_bsum[t] = s[t] - v;
    if (t == NBLK - 1) g_off[N_NODES] = s[t];
}
__global__ void scan3_kernel() {
    __shared__ int s[SCAN_B];
    int t = threadIdx.x;
    int v = blockIdx.x * SCAN_B + t;
    int d = (v < N_NODES) ? (g_degi[v] - 1) : 0;
    s[t] = d;
    __syncthreads();
    for (int off = 1; off < SCAN_B; off <<= 1) {
        int a = (t >= off) ? s[t - off] : 0;
        __syncthreads();
        s[t] += a;
        __syncthreads();
    }
    if (v < N_NODES) {
        g_off[v] = g_bsum[blockIdx.x] + s[t] - d;
        g_cur[v] = 0;
    }
}
__global__ void fill_kernel(const void* ei) {
    int e = blockIdx.x * blockDim.x + threadIdx.x;
    if (e >= N_EDGES) return;
    int s, d;
    if (g_is64) {
        const long long* p = (const long long*)ei;
        s = (int)p[e];
        d = (int)p[N_EDGES + e];
    } else {
        const int* p = (const int*)ei;
        s = p[e];
        d = p[N_EDGES + e];
    }
    int pos = g_off[d] + atomicAdd(&g_cur[d], 1);
    float nm = rsqrtf((float)g_degi[s] * (float)g_degi[d]);
    g_adj[pos] = make_float2(__int_as_float(s), nm);
}

// ================= pipelined bf16x2-split GEMM (BM=128, cp.async double buffer) =================
// EPI: 0 -> fp32 store (bias), 1 -> fp16 half2 store (h for gather)
#define PADU 20

template <int NN, int EPI>
__global__ void __launch_bounds__(256) mma_gemm_pipe(
    const uint32_t* __restrict__ Ah, const uint32_t* __restrict__ Al, int lda_u,
    const uint32_t* __restrict__ Bh, const uint32_t* __restrict__ Bl, int ldb_u,
    const float* __restrict__ bias,
    float* __restrict__ Cf, int ldc,
    uint32_t* __restrict__ Ch, int ldh_u,
    int M, int K)
{
    extern __shared__ uint32_t dyn[];
    constexpr int OA_LO = 128 * PADU;
    constexpr int OB_HI = 2 * 128 * PADU;
    constexpr int OB_LO = OB_HI + NN * PADU;
    constexpr int BUF_U = OB_LO + NN * PADU;

    const int tid = threadIdx.x;
    const int wid = tid >> 5;
    const int lane = tid & 31;
    const int gr = lane >> 2;
    const int gc = lane & 3;
    const int warp_m = wid >> 1;
    const int warp_n = wid & 1;
    const int m0 = blockIdx.x * 128;
    constexpr int NT = NN / 16;

    const uint32_t sbase = smem_u32(dyn);
    const int chunks = K >> 5;

    float acc[2][NT][4];
#pragma unroll
    for (int mt = 0; mt < 2; mt++)
#pragma unroll
        for (int nt = 0; nt < NT; nt++)
#pragma unroll
            for (int j = 0; j < 4; j++) acc[mt][nt][j] = 0.0f;

    auto stage = [&](int c, int buf) {
        const int k0u = c << 4;
        const uint32_t sb = sbase + (uint32_t)buf * BUF_U * 4;
#pragma unroll
        for (int it = 0; it < 2; it++) {
            int idx = tid + it * 256;
            int row = idx >> 2, j = idx & 3;
            bool ok = (m0 + row < M);
            size_t go = ok ? ((size_t)(m0 + row) * lda_u + k0u + j * 4) : 0;
            uint32_t so = (uint32_t)(row * PADU + j * 4) * 4;
            cp_async16(sb + so, Ah + go, ok);
            cp_async16(sb + OA_LO * 4 + so, Al + go, ok);
        }
#pragma unroll
        for (int it = 0; it < NN / 64; it++) {
            int idx = tid + it * 256;
            int row = idx >> 2, j = idx & 3;
            size_t go = (size_t)row * ldb_u + k0u + j * 4;
            uint32_t so = (uint32_t)(row * PADU + j * 4) * 4;
            cp_async16(sb + OB_HI * 4 + so, Bh + go, true);
            cp_async16(sb + OB_LO * 4 + so, Bl + go, true);
        }
        CP_COMMIT();
    };

    stage(0, 0);

    for (int c = 0; c < chunks; c++) {
        const int cur = c & 1;
        if (c + 1 < chunks) {
            stage(c + 1, cur ^ 1);
            CP_WAIT(1);
        } else {
            CP_WAIT(0);
        }
        __syncthreads();

        const uint32_t* sAh = dyn + cur * BUF_U;
        const uint32_t* sAl = sAh + OA_LO;
        const uint32_t* sBh = dyn + cur * BUF_U + OB_HI;
        const uint32_t* sBl = dyn + cur * BUF_U + OB_LO;

#pragma unroll
        for (int s = 0; s < 2; s++) {
            const int kc = s * 8 + gc;
            uint32_t ah[2][4], al[2][4];
#pragma unroll
            for (int mt = 0; mt < 2; mt++) {
                int r = warp_m * 32 + mt * 16 + gr;
                ah[mt][0] = sAh[r * PADU + kc];
                ah[mt][1] = sAh[(r + 8) * PADU + kc];
                ah[mt][2] = sAh[r * PADU + kc + 4];
                ah[mt][3] = sAh[(r + 8) * PADU + kc + 4];
                al[mt][0] = sAl[r * PADU + kc];
                al[mt][1] = sAl[(r + 8) * PADU + kc];
                al[mt][2] = sAl[r * PADU + kc + 4];
                al[mt][3] = sAl[(r + 8) * PADU + kc + 4];
            }
#pragma unroll
            for (int nt = 0; nt < NT; nt++) {
                int n = warp_n * (NN / 2) + nt * 8 + gr;
                uint32_t bh[2], bl[2];
                bh[0] = sBh[n * PADU + kc];
                bh[1] = sBh[n * PADU + kc + 4];
                bl[0] = sBl[n * PADU + kc];
                bl[1] = sBl[n * PADU + kc + 4];
#pragma unroll
                for (int mt = 0; mt < 2; mt++) {
                    mma16816(acc[mt][nt], ah[mt], bh);
                    mma16816(acc[mt][nt], ah[mt], bl);
                    mma16816(acc[mt][nt], al[mt], bh);
                }
            }
        }
        __syncthreads();
    }

#pragma unroll
    for (int mt = 0; mt < 2; mt++) {
#pragma unroll
        for (int nt = 0; nt < NT; nt++) {
            int col = warp_n * (NN / 2) + nt * 8 + 2 * gc;
            float b0 = __ldg(bias + col);
            float b1 = __ldg(bias + col + 1);
#pragma unroll
            for (int half = 0; half < 2; half++) {
                int r = m0 + warp_m * 32 + mt * 16 + gr + half * 8;
                if (r >= M) continue;
                float ox = acc[mt][nt][2 * half + 0] + b0;
                float oy = acc[mt][nt][2 * half + 1] + b1;
                if (EPI == 1) {
                    __half2 p = __floats2half2_rn(ox, oy);
                    Ch[(size_t)r * ldh_u + col / 2] = *(uint32_t*)&p;
                } else {
                    *(float2*)(Cf + (size_t)r * ldc + col) = make_float2(ox, oy);
                }
            }
        }
    }
}

// ================= input-projection GEMM: pipelined (reg-prefetch A, cp.async B) =================
__global__ void __launch_bounds__(256) mma_gemm_inproj(
    const float* __restrict__ A,
    const uint32_t* __restrict__ Bh, const uint32_t* __restrict__ Bl,
    const float* __restrict__ bias,
    uint32_t* __restrict__ Chi, uint32_t* __restrict__ Clo,
    int M)
{
    constexpr int NN = 128;
    constexpr int K = 128;
    extern __shared__ uint32_t dyn[];
    constexpr int OA_LO = 128 * PADU;
    constexpr int OB_HI = 2 * 128 * PADU;
    constexpr int OB_LO = OB_HI + NN * PADU;
    constexpr int BUF_U = OB_LO + NN * PADU;

    const int tid = threadIdx.x;
    const int wid = tid >> 5;
    const int lane = tid & 31;
    const int gr = lane >> 2;
    const int gc = lane & 3;
    const int warp_m = wid >> 1;
    const int warp_n = wid & 1;
    const int m0 = blockIdx.x * 128;
    constexpr int NT = NN / 16;

    const uint32_t sbase = smem_u32(dyn);

    float acc[2][NT][4];
#pragma unroll
    for (int mt = 0; mt < 2; mt++)
#pragma unroll
        for (int nt = 0; nt < NT; nt++)
#pragma unroll
            for (int j = 0; j < 4; j++) acc[mt][nt][j] = 0.0f;

    const int arow = tid >> 1;
    const int aq = (tid & 1) * 4;
    float4 pa[4];
    auto loadA = [&](int c) {
        bool ok = (m0 + arow < M);
        const float* base = A + (size_t)(m0 + arow) * K + c * 32 + aq * 4;
#pragma unroll
        for (int j = 0; j < 4; j++)
            pa[j] = ok ? *(const float4*)(base + j * 4) : make_float4(0, 0, 0, 0);
    };
    auto stageA = [&](int buf) {
        uint32_t* sA = dyn + buf * BUF_U;
        uint32_t* sAlo = sA + OA_LO;
#pragma unroll
        for (int j = 0; j < 4; j++) {
            float h0, h1, h2, h3, l0, l1, l2, l3;
            hilo(pa[j].x, h0, l0); hilo(pa[j].y, h1, l1);
            hilo(pa[j].z, h2, l2); hilo(pa[j].w, h3, l3);
            int base = arow * PADU + 2 * (aq + j);
            sA[base + 0] = pack2(h0, h1);
            sA[base + 1] = pack2(h2, h3);
            sAlo[base + 0] = pack2(l0, l1);
            sAlo[base + 1] = pack2(l2, l3);
        }
    };
    auto stageB = [&](int c, int buf) {
        const int k0u = c << 4;
        const uint32_t sb = sbase + (uint32_t)buf * BUF_U * 4;
#pragma unroll
        for (int it = 0; it < 2; it++) {
            int idx = tid + it * 256;
            int row = idx >> 2, j = idx & 3;
            size_t go = (size_t)row * 64 + k0u + j * 4;
            uint32_t so = (uint32_t)(row * PADU + j * 4) * 4;
            cp_async16(sb + OB_HI * 4 + so, Bh + go, true);
            cp_async16(sb + OB_LO * 4 + so, Bl + go, true);
        }
        CP_COMMIT();
    };

    loadA(0);
    stageB(0, 0);

    for (int c = 0; c < 4; c++) {
        const int cur = c & 1;
        stageA(cur);
        if (c + 1 < 4) {
            loadA(c + 1);
            stageB(c + 1, cur ^ 1);
            CP_WAIT(1);
        } else {
            CP_WAIT(0);
        }
        __syncthreads();

        const uint32_t* sAh = dyn + cur * BUF_U;
        const uint32_t* sAl = sAh + OA_LO;
        const uint32_t* sBh = dyn + cur * BUF_U + OB_HI;
        const uint32_t* sBl = dyn + cur * BUF_U + OB_LO;

#pragma unroll
        for (int s = 0; s < 2; s++) {
            const int kc = s * 8 + gc;
            uint32_t ah[2][4], al[2][4];
#pragma unroll
            for (int mt = 0; mt < 2; mt++) {
                int r = warp_m * 32 + mt * 16 + gr;
                ah[mt][0] = sAh[r * PADU + kc];
                ah[mt][1] = sAh[(r + 8) * PADU + kc];
                ah[mt][2] = sAh[r * PADU + kc + 4];
                ah[mt][3] = sAh[(r + 8) * PADU + kc + 4];
                al[mt][0] = sAl[r * PADU + kc];
                al[mt][1] = sAl[(r + 8) * PADU + kc];
                al[mt][2] = sAl[r * PADU + kc + 4];
                al[mt][3] = sAl[(r + 8) * PADU + kc + 4];
            }
#pragma unroll
            for (int nt = 0; nt < NT; nt++) {
                int n = warp_n * (NN / 2) + nt * 8 + gr;
                uint32_t bh[2], bl[2];
                bh[0] = sBh[n * PADU + kc];
                bh[1] = sBh[n * PADU + kc + 4];
                bl[0] = sBl[n * PADU + kc];
                bl[1] = sBl[n * PADU + kc + 4];
#pragma unroll
                for (int mt = 0; mt < 2; mt++) {
                    mma16816(acc[mt][nt], ah[mt], bh);
                    mma16816(acc[mt][nt], ah[mt], bl);
                    mma16816(acc[mt][nt], al[mt], bh);
                }
            }
        }
        __syncthreads();
    }

#pragma unroll
    for (int mt = 0; mt < 2; mt++) {
#pragma unroll
        for (int nt = 0; nt < NT; nt++) {
            int col = warp_n * (NN / 2) + nt * 8 + 2 * gc;
            float b0 = __ldg(bias + col);
            float b1 = __ldg(bias + col + 1);
#pragma unroll
            for (int half = 0; half < 2; half++) {
                int r = m0 + warp_m * 32 + mt * 16 + gr + half * 8;
                if (r >= M) continue;
                float ox = fmaxf(acc[mt][nt][2 * half + 0] + b0, 0.f);
                float oy = fmaxf(acc[mt][nt][2 * half + 1] + b1, 0.f);
                float hx, lx, hy, ly;
                hilo(ox, hx, lx);
                hilo(oy, hy, ly);
                Chi[(size_t)r * 64 + col / 2] = pack2(hx, hy);
                Clo[(size_t)r * 64 + col / 2] = pack2(lx, ly);
            }
        }
    }
}

// ================= fused aggregation: half-warp per node (fp16 h), 8-deep MLP =================
__global__ void gather_kernel(const uint32_t* __restrict__ hf,
                              uint32_t* __restrict__ cat_hi,
                              uint32_t* __restrict__ cat_lo) {
    int t = blockIdx.x * blockDim.x + threadIdx.x;
    int node = t >> 4;
    int sl = t & 15;
    if (node >= N_NODES) return;

    int beg = g_off[node];
    int end = g_off[node + 1];
    float dinv = 1.0f / (float)(end - beg + 1);

    float acc[8];
    {
        uint4 sv = *(const uint4*)(hf + (size_t)node * 64 + sl * 4);
        float2 a0 = __half22float2(*(__half2*)&sv.x);
        float2 a1 = __half22float2(*(__half2*)&sv.y);
        float2 a2 = __half22float2(*(__half2*)&sv.z);
        float2 a3 = __half22float2(*(__half2*)&sv.w);
        acc[0] = a0.x * dinv; acc[1] = a0.y * dinv;
        acc[2] = a1.x * dinv; acc[3] = a1.y * dinv;
        acc[4] = a2.x * dinv; acc[5] = a2.y * dinv;
        acc[6] = a3.x * dinv; acc[7] = a3.y * dinv;
    }

#define ACCUM(vv, nm) do { \
        float2 _a = __half22float2(*(__half2*)&(vv).x); \
        float2 _b = __half22float2(*(__half2*)&(vv).y); \
        float2 _c = __half22float2(*(__half2*)&(vv).z); \
        float2 _d = __half22float2(*(__half2*)&(vv).w); \
        acc[0] += _a.x * (nm); acc[1] += _a.y * (nm); \
        acc[2] += _b.x * (nm); acc[3] += _b.y * (nm); \
        acc[4] += _c.x * (nm); acc[5] += _c.y * (nm); \
        acc[6] += _d.x * (nm); acc[7] += _d.y * (nm); } while (0)

    int i = beg;
    // 8-deep unrolled main loop: 8 adj + 8 row loads in flight per half-warp
    for (; i + 8 <= end; i += 8) {
        float2 p[8];
        uint4 v[8];
#pragma unroll
        for (int j = 0; j < 8; j++) p[j] = g_adj[i + j];
#pragma unroll
        for (int j = 0; j < 8; j++)
            v[j] = *(const uint4*)(hf + (size_t)__float_as_int(p[j].x) * 64 + sl * 4);
#pragma unroll
        for (int j = 0; j < 8; j++) ACCUM(v[j], p[j].y);
    }
    for (; i + 4 <= end; i += 4) {
        float2 p0 = g_adj[i + 0];
        float2 p1 = g_adj[i + 1];
        float2 p2 = g_adj[i + 2];
        float2 p3 = g_adj[i + 3];
        uint4 v0 = *(const uint4*)(hf + (size_t)__float_as_int(p0.x) * 64 + sl * 4);
        uint4 v1 = *(const uint4*)(hf + (size_t)__float_as_int(p1.x) * 64 + sl * 4);
        uint4 v2 = *(const uint4*)(hf + (size_t)__float_as_int(p2.x) * 64 + sl * 4);
        uint4 v3 = *(const uint4*)(hf + (size_t)__float_as_int(p3.x) * 64 + sl * 4);
        ACCUM(v0, p0.y);
        ACCUM(v1, p1.y);
        ACCUM(v2, p2.y);
        ACCUM(v3, p3.y);
    }
    for (; i < end; i++) {
        float2 p = g_adj[i];
        uint4 v = *(const uint4*)(hf + (size_t)__float_as_int(p.x) * 64 + sl * 4);
        ACCUM(v, p.y);
    }
#undef ACCUM

    uint4 uhi, ulo;
    float hh, ll;
    float h2v[8], l2v[8];
#pragma unroll
    for (int j = 0; j < 8; j++) {
        float r = fmaxf(acc[j], 0.f);
        hilo(r, hh, ll);
        h2v[j] = hh;
        l2v[j] = ll;
    }
    uhi.x = pack2(h2v[0], h2v[1]); uhi.y = pack2(h2v[2], h2v[3]);
    uhi.z = pack2(h2v[4], h2v[5]); uhi.w = pack2(h2v[6], h2v[7]);
    ulo.x = pack2(l2v[0], l2v[1]); ulo.y = pack2(l2v[2], l2v[3]);
    ulo.z = pack2(l2v[4], l2v[5]); ulo.w = pack2(l2v[6], l2v[7]);
    *(uint4*)(cat_hi + (size_t)node * CATU + sl * 4) = uhi;
    *(uint4*)(cat_lo + (size_t)node * CATU + sl * 4) = ulo;
}

// ================= launch =================
extern "C" void kernel_launch(void* const* d_in, const int* in_sizes, int n_in,
                              void* d_out, int out_size) {
    const float* x     = (const float*)d_in[0];
    const void*  ei    = d_in[1];
    const float* W_in  = (const float*)d_in[2];
    const float* b_in  = (const float*)d_in[3];
    const float* Wc    = (const float*)d_in[4];
    const float* bc    = (const float*)d_in[5];
    const float* W_out = (const float*)d_in[6];
    const float* b_out = (const float*)d_in[7];
    float* out = (float*)d_out;

    uint32_t *x0h, *x0l, *hf, *cath, *catl, *wh, *wl;
    cudaGetSymbolAddress((void**)&hf, g_hf);
    cudaGetSymbolAddress((void**)&x0h, g_x0h);
    cudaGetSymbolAddress((void**)&x0l, g_x0l);
    cudaGetSymbolAddress((void**)&cath, g_cath);
    cudaGetSymbolAddress((void**)&catl, g_catl);
    cudaGetSymbolAddress((void**)&wh, g_wh);
    cudaGetSymbolAddress((void**)&wl, g_wl);

    const int SM128 = 2 * (2 * 128 * PADU + 2 * 128 * PADU) * 4;   // 81920
    const int SM64  = 2 * (2 * 128 * PADU + 2 * 64 * PADU) * 4;    // 61440
    cudaFuncSetAttribute((const void*)mma_gemm_pipe<128, 1>, cudaFuncAttributeMaxDynamicSharedMemorySize, SM128);
    cudaFuncSetAttribute((const void*)mma_gemm_pipe<64, 0>,  cudaFuncAttributeMaxDynamicSharedMemorySize, SM64);
    cudaFuncSetAttribute((const void*)mma_gemm_inproj,       cudaFuncAttributeMaxDynamicSharedMemorySize, SM128);

    // fork/join resources — created once on the first (uncaptured) correctness call
    static cudaStream_t s2 = nullptr;
    static cudaEvent_t e1 = nullptr, e2 = nullptr;
    if (!s2) {
        cudaStreamCreateWithFlags(&s2, cudaStreamNonBlocking);
        cudaEventCreateWithFlags(&e1, cudaEventDisableTiming);
        cudaEventCreateWithFlags(&e2, cudaEventDisableTiming);
    }

    const int TB = 256;
    const int M = N_NODES;
    const int GB = (M + 127) / 128;   // 391

    // ---- stream 0: shared init ----
    fused_init_kernel<<<(WU_TOT + TB - 1) / TB, TB>>>(ei, W_in, Wc, W_out);
    cudaEventRecord(e1, 0);

    // ---- branch s2: CSR build (hidden under inproj + GEMM L0) ----
    cudaStreamWaitEvent(s2, e1, 0);
    degcount_kernel<<<(N_EDGES + TB - 1) / TB, TB, 0, s2>>>(ei);
    scan1_kernel<<<NBLK, SCAN_B, 0, s2>>>();
    scan2_kernel<<<1, SCAN_B, 0, s2>>>();
    scan3_kernel<<<NBLK, SCAN_B, 0, s2>>>();
    fill_kernel<<<(N_EDGES + TB - 1) / TB, TB, 0, s2>>>(ei);
    cudaEventRecord(e2, s2);

    // ---- stream 0 (concurrent): input projection + layer-0 GEMM ----
    mma_gemm_inproj<<<GB, 256, SM128>>>(x, wh + WU_IN, wl + WU_IN, b_in, x0h, x0l, M);
    mma_gemm_pipe<128, 1><<<GB, 256, SM128>>>(
        x0h, x0l, 64,
        wh + WU_C, wl + WU_C, 64, bc,
        nullptr, 0, hf, 64, M, HID);

    // ---- join: gather L0 needs the CSR ----
    cudaStreamWaitEvent(0, e2, 0);

    const int gthreads = N_NODES * 16;
    for (int L = 0; L < N_LAYERS; L++) {
        if (L > 0) {
            mma_gemm_pipe<128, 1><<<GB, 256, SM128>>>(
                cath + (size_t)(L - 1) * 64, catl + (size_t)(L - 1) * 64, CATU,
                wh + WU_C + (size_t)L * 8192, wl + WU_C + (size_t)L * 8192, 64,
                bc + (size_t)L * HID,
                nullptr, 0, hf, 64, M, HID);
        }
        gather_kernel<<<(gthreads + TB - 1) / TB, TB>>>(hf, cath + (size_t)L * 64, catl + (size_t)L * 64);
    }

    // ---- final projection: K=512, NN=64, fp32 out ----
    mma_gemm_pipe<64, 0><<<GB, 256, SM64>>>(
        cath, catl, CATU,
        wh + WU_OUT, wl + WU_OUT, 256,
        b_out,
        out, OUT_CH, nullptr, 0, M, CATW);
}